// round 13
// baseline (speedup 1.0000x reference)
#include <cuda_runtime.h>
#include <cuda_fp16.h>
#include <cstdint>

// ---------------- problem constants ----------------
#define NIMG 32
#define CI   128
#define HH   56
#define WW   56
#define CO   256
#define HP   58
#define WP   58
#define PIX  (HH*WW)          // 3136
#define MTOT (NIMG*PIX)       // 100352

// fp16 scratch (static device globals: allowed)
__device__ __align__(1024) __half g_xh[(size_t)NIMG*HP*WP*CI];  // NHWC + halo
__device__ __align__(1024) __half g_wh[(size_t)9*CO*CI];        // [kc][co][ci]

// ---------------- fused prep kernel ----------------
#define TBLK 1792
#define HBLK 32
#define WBLK 36

__global__ void __launch_bounds__(256) prep(const float* __restrict__ x,
                                            const float* __restrict__ W) {
    const int bid = blockIdx.x, tid = threadIdx.x;

    if (bid < TBLK) {
        __shared__ __half s[CI * 58];
        __half2* s2 = reinterpret_cast<__half2*>(s);
        int h = bid % 56, n = bid / 56;
        const float* xp = x + ((size_t)n * CI) * PIX + h * WW;
        for (int id = tid; id < CI * 14; id += 256) {
            int ci = id / 14, w4 = id % 14;
            float4 v = *reinterpret_cast<const float4*>(xp + (size_t)ci * PIX + w4 * 4);
            int si = ci * 29 + w4 * 2;
            s2[si]     = __halves2half2(__float2half_rn(v.x), __float2half_rn(v.y));
            s2[si + 1] = __halves2half2(__float2half_rn(v.z), __float2half_rn(v.w));
        }
        __syncthreads();
        __half2* dst = reinterpret_cast<__half2*>(
            g_xh + ((size_t)((n * HP + h + 1) * WP + 1)) * CI);
        for (int id = tid; id < WW * (CI / 2); id += 256) {
            int w = id >> 6, c2 = id & 63;
            dst[w * (CI / 2) + c2] =
                __halves2half2(s[(2 * c2) * 58 + w], s[(2 * c2 + 1) * 58 + w]);
        }
    } else if (bid < TBLK + HBLK) {
        int n = bid - TBLK;
        uint4 z = make_uint4(0, 0, 0, 0);
        __half* b0 = g_xh + (size_t)(n * HP + 0)  * WP * CI;
        __half* b1 = g_xh + (size_t)(n * HP + 57) * WP * CI;
        for (int i = tid; i < WP * CI / 8; i += 256) {
            reinterpret_cast<uint4*>(b0)[i] = z;
            reinterpret_cast<uint4*>(b1)[i] = z;
        }
        for (int i = tid; i < 56 * 2 * 16; i += 256) {
            int r = i >> 5; int e = (i >> 4) & 1; int q = i & 15;
            __half* eb = g_xh + (size_t)((n * HP + 1 + r) * WP + e * 57) * CI;
            reinterpret_cast<uint4*>(eb)[q] = z;
        }
    } else {
        int i0 = (bid - TBLK - HBLK) * 8192;
        for (int k = tid; k < 8192; k += 256) {
            int i = i0 + k;
            int kw = i % 3; int t = i / 3;
            int kh = t % 3; t /= 3;
            int ci = t % CI; int co = t / CI;
            float v = rintf(W[i] * 128.0f);      // exact integer, exact in fp16
            g_wh[(size_t)((kh * 3 + kw) * CO + co) * CI + ci] = __float2half_rn(v);
        }
    }
}

// ---------------- persistent GEMM (HMMA) ----------------
// Grid: 296 CTAs (2/SM). 3136 tiles of 64 pix x 128 co; CTA c owns c, c+296, ...
// (10 or 11 tiles each -> tail quantization 13% -> 3.8%).
// CTA: 128 threads, 4 warps (2m x 2n), warp tile 32x64, mma m16n8k16 f32.f16.
// K: 18 chunks of 64 ci. 3-stage cp.async pipeline. co_base fixed per CTA.

#define ROWB    144                 // 128B data + 16B pad
#define BOFF    (64 * ROWB)         // B tile offset within a stage (A = 64 rows)
#define STAGE   (192 * ROWB)        // 27648
#define NSTAGE  3
#define NT      18
#define HDR     512
#define SMEM_DYN (HDR + NSTAGE * STAGE)   // 83456 -> 2 CTAs/SM
#define NCTA    296
#define NTILES  3136

__device__ __forceinline__ void ldsm_x4(uint32_t addr, uint32_t& r0, uint32_t& r1,
                                        uint32_t& r2, uint32_t& r3) {
    asm volatile("ldmatrix.sync.aligned.m8n8.x4.shared.b16 {%0,%1,%2,%3}, [%4];\n"
                 : "=r"(r0), "=r"(r1), "=r"(r2), "=r"(r3) : "r"(addr));
}

__global__ void __launch_bounds__(128, 2) qconv_gemm(const float* __restrict__ bias,
                                                     float* __restrict__ out) {
    extern __shared__ char smem[];
    float* bq = reinterpret_cast<float*>(smem);
    const uint32_t sb = (uint32_t)__cvta_generic_to_shared(smem);

    const int tid = threadIdx.x;
    const int cta = blockIdx.x;
    const int co_base = (cta & 1) * 128;     // invariant under tile += 296 (even)

    bq[tid] = rintf(bias[co_base + tid] * 128.0f);

    const char* xh = reinterpret_cast<const char*>(g_xh);
    const char* wh = reinterpret_cast<const char*>(g_wh);
    const int row0 = tid >> 3, ch0 = (tid & 7) * 16;
    const char* bSrc0 = wh + (size_t)(co_base + row0) * 256 + ch0;
    const uint32_t aDst0 = sb + HDR + row0 * ROWB + ch0;
    const uint32_t bDst0 = sb + HDR + BOFF + row0 * ROWB + ch0;

    const int warp = tid >> 5, lane = tid & 31;
    const int warp_m = (warp & 1) * 32;
    const int warp_n = (warp >> 1) * 64;

    const uint32_t aoff0 = (uint32_t)((warp_m + (lane & 15)) * ROWB + (lane >> 4) * 16);
    const uint32_t boff0 = (uint32_t)(BOFF + (warp_n + (lane & 7) + ((lane >> 4) << 3)) * ROWB
                                      + ((lane >> 3) & 1) * 16);

    // persistent loop over this CTA's tiles
    #pragma unroll 1
    for (int tile = cta; tile < NTILES; tile += NCTA) {
        const int m_base = (tile >> 1) * 64;

        // per-tile A gmem endpoints (rows row0 + 16*i in [0,64))
        const char* aSrc[4];
        #pragma unroll
        for (int i = 0; i < 4; i++) {
            int p = m_base + row0 + 16 * i;
            int ni = p / PIX; int rem = p - ni * PIX;
            int h = rem / WW; int w = rem - h * WW;
            aSrc[i] = xh + ((size_t)((ni * HP + h) * WP + w)) * 256 + ch0;
        }

        auto issue = [&](int t, int slot) {
            int kc = t >> 1, hf = t & 1;
            int kh = kc / 3, kw = kc - kh * 3;
            uint32_t aoff = (uint32_t)((kh * WP + kw) * 256 + hf * 128);
            uint32_t boff = (uint32_t)(kc * (CO * 256) + hf * 128);
            uint32_t so = slot * STAGE;
            #pragma unroll
            for (int i = 0; i < 4; i++)
                asm volatile("cp.async.cg.shared.global [%0], [%1], 16;\n"
                             :: "r"(aDst0 + so + i * (16 * ROWB)), "l"(aSrc[i] + aoff));
            #pragma unroll
            for (int i = 0; i < 8; i++)      // B rows row0 + 16*i in [0,128)
                asm volatile("cp.async.cg.shared.global [%0], [%1], 16;\n"
                             :: "r"(bDst0 + so + i * (16 * ROWB)), "l"(bSrc0 + boff + (size_t)i * 4096));
            asm volatile("cp.async.commit_group;\n" ::: "memory");
        };

        float acc[2][8][4];
        #pragma unroll
        for (int i = 0; i < 2; i++)
            #pragma unroll
            for (int j = 0; j < 8; j++)
                #pragma unroll
                for (int k = 0; k < 4; k++) acc[i][j][k] = 0.0f;

        // prologue: fill 2 of 3 stages
        issue(0, 0); issue(1, 1);

        #pragma unroll 1
        for (int t = 0; t < NT; t++) {
            asm volatile("cp.async.wait_group 1;\n" ::: "memory");
            __syncthreads();
            int tn = t + 2;
            if (tn < NT) issue(tn, tn - (tn / 3) * 3);
            else asm volatile("cp.async.commit_group;\n" ::: "memory");

            uint32_t sA = sb + HDR + (t - (t / 3) * 3) * STAGE;
            #pragma unroll
            for (int k16 = 0; k16 < 4; k16++) {
                uint32_t a[2][4];
                #pragma unroll
                for (int mf = 0; mf < 2; mf++)
                    ldsm_x4(sA + aoff0 + mf * (16 * ROWB) + k16 * 32,
                            a[mf][0], a[mf][1], a[mf][2], a[mf][3]);
                uint32_t b[8][2];
                #pragma unroll
                for (int j = 0; j < 4; j++) {
                    uint32_t r0, r1, r2, r3;
                    ldsm_x4(sA + boff0 + j * (16 * ROWB) + k16 * 32, r0, r1, r2, r3);
                    b[2*j][0] = r0; b[2*j][1] = r1; b[2*j+1][0] = r2; b[2*j+1][1] = r3;
                }
                #pragma unroll
                for (int mf = 0; mf < 2; mf++)
                    #pragma unroll
                    for (int nf = 0; nf < 8; nf++) {
                        asm volatile(
                            "mma.sync.aligned.m16n8k16.row.col.f32.f16.f16.f32 "
                            "{%0,%1,%2,%3}, {%4,%5,%6,%7}, {%8,%9}, {%0,%1,%2,%3};\n"
                            : "+f"(acc[mf][nf][0]), "+f"(acc[mf][nf][1]),
                              "+f"(acc[mf][nf][2]), "+f"(acc[mf][nf][3])
                            : "r"(a[mf][0]), "r"(a[mf][1]), "r"(a[mf][2]), "r"(a[mf][3]),
                              "r"(b[nf][0]), "r"(b[nf][1]));
                    }
            }
        }

        // epilogue: out[n][co][h][w] = acc/128 + round(b*128)
        const float inv = 0.0078125f;
        #pragma unroll
        for (int mf = 0; mf < 2; mf++) {
            #pragma unroll
            for (int hsel = 0; hsel < 2; hsel++) {
                int m = warp_m + mf * 16 + (lane >> 2) + hsel * 8;
                int p = m_base + m;
                int ni = p / PIX; int rem = p - ni * PIX;
                int h = rem / WW; int w = rem - h * WW;
                float* op = out + (size_t)ni * CO * PIX + h * WW + w;
                #pragma unroll
                for (int nf = 0; nf < 8; nf++) {
                    int col = warp_n + nf * 8 + 2 * (lane & 3);
                    int co  = co_base + col;
                    op[(size_t)co * PIX]       = acc[mf][nf][hsel*2 + 0] * inv + bq[col];
                    op[(size_t)(co + 1) * PIX] = acc[mf][nf][hsel*2 + 1] * inv + bq[col + 1];
                }
            }
        }
        __syncthreads();   // all warps done with smem stages before next tile refills
    }
}

// ---------------- launch ----------------
extern "C" void kernel_launch(void* const* d_in, const int* in_sizes, int n_in,
                              void* d_out, int out_size) {
    const float* x = (const float*)d_in[0];
    const float* W = (const float*)d_in[1];
    const float* b = (const float*)d_in[2];
    float* out = (float*)d_out;

    prep<<<TBLK + HBLK + WBLK, 256>>>(x, W);

    cudaFuncSetAttribute(qconv_gemm, cudaFuncAttributeMaxDynamicSharedMemorySize, SMEM_DYN);
    qconv_gemm<<<NCTA, 128, SMEM_DYN>>>(b, out);
}

// round 14
// speedup vs baseline: 1.0072x; 1.0072x over previous
#include <cuda_runtime.h>
#include <cuda_fp16.h>
#include <cstdint>

// ---------------- problem constants ----------------
#define NIMG 32
#define CI   128
#define HH   56
#define WW   56
#define CO   256
#define HP   58
#define WP   58
#define PIX  (HH*WW)          // 3136
#define MTOT (NIMG*PIX)       // 100352
#define NCTA_G 1568           // 784 pixel-blocks x 2 co-halves
#define NROWT  (NIMG*HP)      // 1856 padded-row tasks

// fp16 scratch + dataflow flags (static device globals: allowed)
__device__ __align__(1024) __half g_xh[(size_t)NIMG*HP*WP*CI];  // NHWC + halo
__device__ __align__(1024) __half g_wh[(size_t)9*CO*CI];        // [kc][co][ci]
__device__ int g_xflag[NROWT];   // padded row (n,hp) ready
__device__ int g_wflag[32];      // weight chunk of 8 co (all kc) ready

__global__ void reset_flags() {
    int i = blockIdx.x * 256 + threadIdx.x;
    if (i < NROWT) g_xflag[i] = 0;
    if (i < 32)    g_wflag[i] = 0;
}

// ---------------- GEMM tiling constants (round-6 champion) ----------------
#define ROWB    144                 // 128B data + 16B pad
#define BOFF    (128 * ROWB)        // B tile offset within a stage
#define STAGE   (256 * ROWB)        // 36864
#define NT      18
#define HDR     512
#define SMEM_DYN (HDR + 3 * STAGE)  // 111104 -> 2 CTAs/SM

__device__ __forceinline__ void ldsm_x4(uint32_t addr, uint32_t& r0, uint32_t& r1,
                                        uint32_t& r2, uint32_t& r3) {
    asm volatile("ldmatrix.sync.aligned.m8n8.x4.shared.b16 {%0,%1,%2,%3}, [%4];\n"
                 : "=r"(r0), "=r"(r1), "=r"(r2), "=r"(r3) : "r"(addr));
}

__global__ void __launch_bounds__(256, 2) qconv_fused(const float* __restrict__ x,
                                                      const float* __restrict__ W,
                                                      const float* __restrict__ bias,
                                                      float* __restrict__ out) {
    extern __shared__ char smem[];
    const uint32_t sb = (uint32_t)__cvta_generic_to_shared(smem);
    const int tid = threadIdx.x;
    const int bidx = blockIdx.x;
    const int co_base = (bidx & 1) * 128;
    const int m_base  = (bidx >> 1) * 128;

    // ================= producer phase =================
    // (a) weight chunk: CTAs 0..31 each convert co range [b*8, b*8+8) for all 9 kc
    if (bidx < 32) {
        for (int k = tid; k < 8 * CI * 9; k += 256) {
            int kw = k % 3; int t = k / 3;
            int kh = t % 3; t /= 3;
            int ci = t % CI; int col = t / CI;           // 0..7
            int co = bidx * 8 + col;
            float v = rintf(W[(size_t)co * 1152 + ci * 9 + kh * 3 + kw] * 128.0f);
            g_wh[((size_t)(kh * 3 + kw) * CO + co) * CI + ci] = __float2half_rn(v);
        }
        __syncthreads();
        __threadfence();
        if (tid == 0) *(volatile int*)&g_wflag[bidx] = 1;
    }

    // (b) padded-row tasks: CTA b owns rows [1856b/1568, 1856(b+1)/1568)
    {
        int t0 = (NROWT * bidx) / NCTA_G;
        int t1 = (NROWT * (bidx + 1)) / NCTA_G;
        for (int r = t0; r < t1; r++) {
            int n = r / HP, hp = r % HP;
            __half* rowp = g_xh + (size_t)r * (WP * CI);
            if (hp == 0 || hp == HP - 1) {
                uint4 z = make_uint4(0, 0, 0, 0);
                for (int i = tid; i < WP * CI / 8; i += 256)
                    reinterpret_cast<uint4*>(rowp)[i] = z;
            } else {
                int h = hp - 1;
                __half* s = reinterpret_cast<__half*>(smem);   // CI*58 halves
                __half2* s2 = reinterpret_cast<__half2*>(s);
                const float* xp = x + ((size_t)n * CI) * PIX + h * WW;
                for (int id = tid; id < CI * 14; id += 256) {
                    int ci = id / 14, w4 = id % 14;
                    float4 v = *reinterpret_cast<const float4*>(xp + (size_t)ci * PIX + w4 * 4);
                    int si = ci * 29 + w4 * 2;
                    s2[si]     = __halves2half2(__float2half_rn(v.x), __float2half_rn(v.y));
                    s2[si + 1] = __halves2half2(__float2half_rn(v.z), __float2half_rn(v.w));
                }
                __syncthreads();
                // content: wp 1..56 (64 half2 per pixel)
                __half2* dst = reinterpret_cast<__half2*>(rowp + CI);
                for (int id = tid; id < WW * (CI / 2); id += 256) {
                    int w = id >> 6, c2 = id & 63;
                    dst[w * (CI / 2) + c2] =
                        __halves2half2(s[(2 * c2) * 58 + w], s[(2 * c2 + 1) * 58 + w]);
                }
                // edges wp=0 and wp=57
                if (tid < 32) {
                    uint4 z = make_uint4(0, 0, 0, 0);
                    int e = tid >> 4, q = tid & 15;
                    reinterpret_cast<uint4*>(rowp + (size_t)e * 57 * CI)[q] = z;
                }
            }
            __syncthreads();
            __threadfence();
            if (tid == 0) *(volatile int*)&g_xflag[r] = 1;
            __syncthreads();     // smem reuse safety for next task
        }
    }

    // ================= consumer spin =================
    {
        int pl = m_base + 127;
        int n1 = m_base / PIX, h1 = (m_base - n1 * PIX) / WW;
        int n2 = pl / PIX,     h2 = (pl - n2 * PIX) / WW;
        int r0 = n1 * HP + h1;
        int r1 = n2 * HP + h2 + 2;                 // inclusive
        int nr = r1 - r0 + 1;                      // <= 8
        if (tid < 16) {
            volatile int* f = &g_wflag[(co_base >> 3) + tid];
            while (*f == 0) __nanosleep(128);
        } else if (tid < 16 + nr) {
            volatile int* f = &g_xflag[r0 + tid - 16];
            while (*f == 0) __nanosleep(128);
        }
        __threadfence();
        __syncthreads();
    }

    // ================= GEMM (round-6 champion body) =================
    float* bq = reinterpret_cast<float*>(smem);
    if (tid < 128) bq[tid] = rintf(bias[co_base + tid] * 128.0f);

    const char* xh = reinterpret_cast<const char*>(g_xh);
    const char* wh = reinterpret_cast<const char*>(g_wh);
    const int row0 = tid >> 3, ch0 = (tid & 7) * 16;
    const char* aSrc[4];
    #pragma unroll
    for (int i = 0; i < 4; i++) {
        int p = m_base + row0 + 32 * i;
        int ni = p / PIX; int rem = p - ni * PIX;
        int h = rem / WW; int w = rem - h * WW;
        aSrc[i] = xh + ((size_t)((ni * HP + h) * WP + w)) * 256 + ch0;  // window top-left
    }
    const char* bSrc0 = wh + (size_t)(co_base + row0) * 256 + ch0;
    const uint32_t aDst0 = sb + HDR + row0 * ROWB + ch0;
    const uint32_t bDst0 = sb + HDR + BOFF + row0 * ROWB + ch0;

    auto issue = [&](int t, int slot) {
        int kc = t >> 1, hf = t & 1;
        int kh = kc / 3, kw = kc - kh * 3;
        uint32_t aoff = (uint32_t)((kh * WP + kw) * 256 + hf * 128);
        uint32_t boff = (uint32_t)(kc * (CO * 256) + hf * 128);
        uint32_t so = slot * STAGE;
        #pragma unroll
        for (int i = 0; i < 4; i++)
            asm volatile("cp.async.cg.shared.global [%0], [%1], 16;\n"
                         :: "r"(aDst0 + so + i * (32 * ROWB)), "l"(aSrc[i] + aoff));
        #pragma unroll
        for (int i = 0; i < 4; i++)
            asm volatile("cp.async.cg.shared.global [%0], [%1], 16;\n"
                         :: "r"(bDst0 + so + i * (32 * ROWB)), "l"(bSrc0 + boff + (size_t)i * 8192));
        asm volatile("cp.async.commit_group;\n" ::: "memory");
    };

    const int warp = tid >> 5, lane = tid & 31;
    const int warp_m = (warp & 3) * 32;
    const int warp_n = (warp >> 2) * 64;

    float acc[2][8][4];
    #pragma unroll
    for (int i = 0; i < 2; i++)
        #pragma unroll
        for (int j = 0; j < 8; j++)
            #pragma unroll
            for (int k = 0; k < 4; k++) acc[i][j][k] = 0.0f;

    const uint32_t aoff0 = (uint32_t)((warp_m + (lane & 15)) * ROWB + (lane >> 4) * 16);
    const uint32_t boff0 = (uint32_t)(BOFF + (warp_n + (lane & 7) + ((lane >> 4) << 3)) * ROWB
                                      + ((lane >> 3) & 1) * 16);

    __syncthreads();            // bq + smem handoff from prep
    issue(0, 0); issue(1, 1);   // prologue: fill 2 of 3 stages

    #pragma unroll 1
    for (int t = 0; t < NT; t++) {
        asm volatile("cp.async.wait_group 1;\n" ::: "memory");
        __syncthreads();
        int tn = t + 2;
        if (tn < NT) issue(tn, tn - (tn / 3) * 3);
        else asm volatile("cp.async.commit_group;\n" ::: "memory");  // keep group count

        uint32_t sA = sb + HDR + (t - (t / 3) * 3) * STAGE;
        #pragma unroll
        for (int k16 = 0; k16 < 4; k16++) {
            uint32_t a[2][4];
            #pragma unroll
            for (int mf = 0; mf < 2; mf++)
                ldsm_x4(sA + aoff0 + mf * (16 * ROWB) + k16 * 32,
                        a[mf][0], a[mf][1], a[mf][2], a[mf][3]);
            uint32_t b[8][2];
            #pragma unroll
            for (int j = 0; j < 4; j++) {
                uint32_t r0, r1, r2, r3;
                ldsm_x4(sA + boff0 + j * (16 * ROWB) + k16 * 32, r0, r1, r2, r3);
                b[2*j][0] = r0; b[2*j][1] = r1; b[2*j+1][0] = r2; b[2*j+1][1] = r3;
            }
            #pragma unroll
            for (int mf = 0; mf < 2; mf++)
                #pragma unroll
                for (int nf = 0; nf < 8; nf++) {
                    asm volatile(
                        "mma.sync.aligned.m16n8k16.row.col.f32.f16.f16.f32 "
                        "{%0,%1,%2,%3}, {%4,%5,%6,%7}, {%8,%9}, {%0,%1,%2,%3};\n"
                        : "+f"(acc[mf][nf][0]), "+f"(acc[mf][nf][1]),
                          "+f"(acc[mf][nf][2]), "+f"(acc[mf][nf][3])
                        : "r"(a[mf][0]), "r"(a[mf][1]), "r"(a[mf][2]), "r"(a[mf][3]),
                          "r"(b[nf][0]), "r"(b[nf][1]));
                }
        }
    }

    // epilogue: out[n][co][h][w] = acc/128 + round(b*128)
    const float inv = 0.0078125f;
    #pragma unroll
    for (int mf = 0; mf < 2; mf++) {
        #pragma unroll
        for (int hsel = 0; hsel < 2; hsel++) {
            int m = warp_m + mf * 16 + (lane >> 2) + hsel * 8;
            int p = m_base + m;
            int ni = p / PIX; int rem = p - ni * PIX;
            int h = rem / WW; int w = rem - h * WW;
            float* op = out + (size_t)ni * CO * PIX + h * WW + w;
            #pragma unroll
            for (int nf = 0; nf < 8; nf++) {
                int col = warp_n + nf * 8 + 2 * (lane & 3);
                int co  = co_base + col;
                op[(size_t)co * PIX]       = acc[mf][nf][hsel*2 + 0] * inv + bq[col];
                op[(size_t)(co + 1) * PIX] = acc[mf][nf][hsel*2 + 1] * inv + bq[col + 1];
            }
        }
    }
}

// ---------------- launch ----------------
extern "C" void kernel_launch(void* const* d_in, const int* in_sizes, int n_in,
                              void* d_out, int out_size) {
    const float* x = (const float*)d_in[0];
    const float* W = (const float*)d_in[1];
    const float* b = (const float*)d_in[2];
    float* out = (float*)d_out;

    reset_flags<<<8, 256>>>();

    cudaFuncSetAttribute(qconv_fused, cudaFuncAttributeMaxDynamicSharedMemorySize, SMEM_DYN);
    qconv_fused<<<NCTA_G, 256, SMEM_DYN>>>(x, W, b, out);
}

// round 15
// speedup vs baseline: 1.1659x; 1.1576x over previous
#include <cuda_runtime.h>
#include <cuda_fp16.h>
#include <cstdint>

// ---------------- problem constants ----------------
#define NIMG 32
#define CI   128
#define HH   56
#define WW   56
#define CO   256
#define PIX  (HH*WW)          // 3136
#define MTOT (NIMG*PIX)       // 100352

// fp16 scratch (static device globals: allowed). Unpadded NHWC.
__device__ __align__(1024) __half g_xh[(size_t)MTOT*CI];   // [n,h,w][ci] (25.7 MB)
__device__ __align__(1024) __half g_wh[(size_t)9*CO*CI];   // [kc][co][ci]

// ---------------- fused prep kernel ----------------
// blocks [0, 1792): transpose one (n,h) row  (h = bid%56, n = bid/56)
// blocks [1792, 1828): convert 8192 weight elements each
#define TBLK 1792
#define WBLK 36

__global__ void __launch_bounds__(256) prep(const float* __restrict__ x,
                                            const float* __restrict__ W) {
    const int bid = blockIdx.x, tid = threadIdx.x;

    if (bid < TBLK) {
        // NCHW fp32 -> NHWC fp16 for one (n, h) row, via smem transpose
        __shared__ __half s[CI * 58];
        __half2* s2 = reinterpret_cast<__half2*>(s);
        int h = bid % 56, n = bid / 56;
        const float* xp = x + ((size_t)n * CI) * PIX + h * WW;
        for (int id = tid; id < CI * 14; id += 256) {
            int ci = id / 14, w4 = id % 14;
            float4 v = *reinterpret_cast<const float4*>(xp + (size_t)ci * PIX + w4 * 4);
            int si = ci * 29 + w4 * 2;
            s2[si]     = __halves2half2(__float2half_rn(v.x), __float2half_rn(v.y));
            s2[si + 1] = __halves2half2(__float2half_rn(v.z), __float2half_rn(v.w));
        }
        __syncthreads();
        __half2* dst = reinterpret_cast<__half2*>(
            g_xh + ((size_t)(n * PIX + h * WW)) * CI);
        for (int id = tid; id < WW * (CI / 2); id += 256) {
            int w = id >> 6, c2 = id & 63;
            dst[w * (CI / 2) + c2] =
                __halves2half2(s[(2 * c2) * 58 + w], s[(2 * c2 + 1) * 58 + w]);
        }
    } else {
        // weights: round(W*128) -> fp16, layout [kc][co][ci]
        int i0 = (bid - TBLK) * 8192;
        for (int k = tid; k < 8192; k += 256) {
            int i = i0 + k;
            int kw = i % 3; int t = i / 3;
            int kh = t % 3; t /= 3;
            int ci = t % CI; int co = t / CI;
            float v = rintf(W[i] * 128.0f);      // exact integer, exact in fp16
            g_wh[(size_t)((kh * 3 + kw) * CO + co) * CI + ci] = __float2half_rn(v);
        }
    }
}

// ---------------- GEMM (HMMA, 2 CTAs/SM, zero-fill borders) ----------------
// CTA: 128 pix x 128 co, 256 threads. K: 18 chunks of 64 ci (9 taps x 2 halves).
// 8 warps 4m x 2n, warp tile 32x64, mma m16n8k16 f32.f16. 2 CTAs resident/SM.
// Out-of-image taps are zero-filled by cp.async src_size=0 (no padded scratch).

#define ROWB    144                 // 128B data + 16B pad
#define BOFF    (128 * ROWB)        // B tile offset within a stage
#define STAGE   (256 * ROWB)        // 36864
#define NT      18
#define HDR     512
#define SMEM_DYN (HDR + 3 * STAGE)  // 111104 -> 2 CTAs/SM

__device__ __forceinline__ void ldsm_x4(uint32_t addr, uint32_t& r0, uint32_t& r1,
                                        uint32_t& r2, uint32_t& r3) {
    asm volatile("ldmatrix.sync.aligned.m8n8.x4.shared.b16 {%0,%1,%2,%3}, [%4];\n"
                 : "=r"(r0), "=r"(r1), "=r"(r2), "=r"(r3) : "r"(addr));
}

__global__ void __launch_bounds__(256, 2) qconv_gemm(const float* __restrict__ bias,
                                                     float* __restrict__ out) {
    extern __shared__ char smem[];
    float* bq = reinterpret_cast<float*>(smem);
    const uint32_t sb = (uint32_t)__cvta_generic_to_shared(smem);

    const int tid = threadIdx.x;
    const int m_base  = blockIdx.x * 128;
    const int co_base = blockIdx.y * 128;

    if (tid < 128) bq[tid] = rintf(bias[co_base + tid] * 128.0f);

    // cp.async endpoints. A pieces: pixel p_i = m_base + row0 + 32*i, constant
    // address stride 8192 B in unpadded NHWC. Per-piece 9-bit tap-validity mask.
    const char* xh = reinterpret_cast<const char*>(g_xh);
    const char* wh = reinterpret_cast<const char*>(g_wh);
    const int row0 = tid >> 3, ch0 = (tid & 7) * 16;
    const char* aSrc0 = xh + (size_t)(m_base + row0) * 256 + ch0;
    uint32_t amask[4];
    #pragma unroll
    for (int i = 0; i < 4; i++) {
        int p = m_base + row0 + 32 * i;
        int rem = p % PIX;
        int h = rem / WW, w = rem - (rem / WW) * WW;
        uint32_t m = 0;
        #pragma unroll
        for (int kc = 0; kc < 9; kc++) {
            int kh = kc / 3, kw = kc % 3;
            if ((unsigned)(h + kh - 1) < 56u && (unsigned)(w + kw - 1) < 56u)
                m |= (1u << kc);
        }
        amask[i] = m;
    }
    const char* bSrc0 = wh + (size_t)(co_base + row0) * 256 + ch0;
    const uint32_t aDst0 = sb + HDR + row0 * ROWB + ch0;
    const uint32_t bDst0 = sb + HDR + BOFF + row0 * ROWB + ch0;

    // issue one K-chunk's loads into a stage slot; chunk t: kc = t>>1, half = t&1
    auto issue = [&](int t, int slot) {
        int kc = t >> 1, hf = t & 1;
        int kh = kc / 3, kw = kc - kh * 3;
        int aoff = ((kh - 1) * WW + (kw - 1)) * 256 + hf * 128;   // signed, may be < 0
        uint32_t boff = (uint32_t)(kc * (CO * 256) + hf * 128);
        uint32_t so = slot * STAGE;
        #pragma unroll
        for (int i = 0; i < 4; i++) {
            uint32_t sz = ((amask[i] >> kc) & 1u) << 4;           // 16 or 0 (zero-fill)
            asm volatile("cp.async.cg.shared.global [%0], [%1], 16, %2;\n"
                         :: "r"(aDst0 + so + i * (32 * ROWB)),
                            "l"(aSrc0 + (size_t)i * 8192 + aoff), "r"(sz));
        }
        #pragma unroll
        for (int i = 0; i < 4; i++)
            asm volatile("cp.async.cg.shared.global [%0], [%1], 16;\n"
                         :: "r"(bDst0 + so + i * (32 * ROWB)), "l"(bSrc0 + boff + (size_t)i * 8192));
        asm volatile("cp.async.commit_group;\n" ::: "memory");
    };

    const int warp = tid >> 5, lane = tid & 31;
    const int warp_m = (warp & 3) * 32;
    const int warp_n = (warp >> 2) * 64;

    float acc[2][8][4];
    #pragma unroll
    for (int i = 0; i < 2; i++)
        #pragma unroll
        for (int j = 0; j < 8; j++)
            #pragma unroll
            for (int k = 0; k < 4; k++) acc[i][j][k] = 0.0f;

    const uint32_t aoff0 = (uint32_t)((warp_m + (lane & 15)) * ROWB + (lane >> 4) * 16);
    const uint32_t boff0 = (uint32_t)(BOFF + (warp_n + (lane & 7) + ((lane >> 4) << 3)) * ROWB
                                      + ((lane >> 3) & 1) * 16);

    // prologue: fill 2 of 3 stages
    issue(0, 0); issue(1, 1);

    #pragma unroll 1
    for (int t = 0; t < NT; t++) {
        asm volatile("cp.async.wait_group 1;\n" ::: "memory");
        __syncthreads();
        int tn = t + 2;
        if (tn < NT) issue(tn, tn - (tn / 3) * 3);
        else asm volatile("cp.async.commit_group;\n" ::: "memory");  // keep group count

        uint32_t sA = sb + HDR + (t - (t / 3) * 3) * STAGE;
        #pragma unroll
        for (int k16 = 0; k16 < 4; k16++) {
            uint32_t a[2][4];
            #pragma unroll
            for (int mf = 0; mf < 2; mf++)
                ldsm_x4(sA + aoff0 + mf * (16 * ROWB) + k16 * 32,
                        a[mf][0], a[mf][1], a[mf][2], a[mf][3]);
            uint32_t b[8][2];
            #pragma unroll
            for (int j = 0; j < 4; j++) {
                uint32_t r0, r1, r2, r3;
                ldsm_x4(sA + boff0 + j * (16 * ROWB) + k16 * 32, r0, r1, r2, r3);
                b[2*j][0] = r0; b[2*j][1] = r1; b[2*j+1][0] = r2; b[2*j+1][1] = r3;
            }
            #pragma unroll
            for (int mf = 0; mf < 2; mf++)
                #pragma unroll
                for (int nf = 0; nf < 8; nf++) {
                    asm volatile(
                        "mma.sync.aligned.m16n8k16.row.col.f32.f16.f16.f32 "
                        "{%0,%1,%2,%3}, {%4,%5,%6,%7}, {%8,%9}, {%0,%1,%2,%3};\n"
                        : "+f"(acc[mf][nf][0]), "+f"(acc[mf][nf][1]),
                          "+f"(acc[mf][nf][2]), "+f"(acc[mf][nf][3])
                        : "r"(a[mf][0]), "r"(a[mf][1]), "r"(a[mf][2]), "r"(a[mf][3]),
                          "r"(b[nf][0]), "r"(b[nf][1]));
                }
        }
    }

    // epilogue: out[n][co][h][w] = acc/128 + round(b*128)
    const float inv = 0.0078125f;
    #pragma unroll
    for (int mf = 0; mf < 2; mf++) {
        #pragma unroll
        for (int hsel = 0; hsel < 2; hsel++) {
            int m = warp_m + mf * 16 + (lane >> 2) + hsel * 8;
            int p = m_base + m;
            int ni = p / PIX; int rem = p - ni * PIX;
            int h = rem / WW; int w = rem - h * WW;
            float* op = out + (size_t)ni * CO * PIX + h * WW + w;
            #pragma unroll
            for (int nf = 0; nf < 8; nf++) {
                int col = warp_n + nf * 8 + 2 * (lane & 3);
                int co  = co_base + col;
                op[(size_t)co * PIX]       = acc[mf][nf][hsel*2 + 0] * inv + bq[col];
                op[(size_t)(co + 1) * PIX] = acc[mf][nf][hsel*2 + 1] * inv + bq[col + 1];
            }
        }
    }
}

// ---------------- launch ----------------
extern "C" void kernel_launch(void* const* d_in, const int* in_sizes, int n_in,
                              void* d_out, int out_size) {
    const float* x = (const float*)d_in[0];
    const float* W = (const float*)d_in[1];
    const float* b = (const float*)d_in[2];
    float* out = (float*)d_out;

    prep<<<TBLK + WBLK, 256>>>(x, W);

    cudaFuncSetAttribute(qconv_gemm, cudaFuncAttributeMaxDynamicSharedMemorySize, SMEM_DYN);
    qconv_gemm<<<dim3(MTOT / 128, CO / 128), 256, SMEM_DYN>>>(b, out);
}

// round 16
// speedup vs baseline: 1.2729x; 1.0917x over previous
#include <cuda_runtime.h>
#include <cuda_fp16.h>
#include <cstdint>

// ---------------- problem constants ----------------
#define NIMG 32
#define CI   128
#define HH   56
#define WW   56
#define CO   256
#define HP   58
#define WP   58
#define PIX  (HH*WW)          // 3136
#define MTOT (NIMG*PIX)       // 100352

// fp16 scratch (static device globals: allowed)
__device__ __align__(1024) __half g_xh[(size_t)NIMG*HP*WP*CI];  // NHWC + halo
__device__ __align__(1024) __half g_wh[(size_t)9*CO*CI];        // [kc][co][ci]

// ---------------- fused prep kernel (champion, unchanged) ----------------
#define TBLK 1792
#define HBLK 32
#define WBLK 36

__global__ void __launch_bounds__(256) prep(const float* __restrict__ x,
                                            const float* __restrict__ W) {
    const int bid = blockIdx.x, tid = threadIdx.x;

    if (bid < TBLK) {
        __shared__ __half s[CI * 58];
        __half2* s2 = reinterpret_cast<__half2*>(s);
        int h = bid % 56, n = bid / 56;
        const float* xp = x + ((size_t)n * CI) * PIX + h * WW;
        for (int id = tid; id < CI * 14; id += 256) {
            int ci = id / 14, w4 = id % 14;
            float4 v = *reinterpret_cast<const float4*>(xp + (size_t)ci * PIX + w4 * 4);
            int si = ci * 29 + w4 * 2;
            s2[si]     = __halves2half2(__float2half_rn(v.x), __float2half_rn(v.y));
            s2[si + 1] = __halves2half2(__float2half_rn(v.z), __float2half_rn(v.w));
        }
        __syncthreads();
        __half2* dst = reinterpret_cast<__half2*>(
            g_xh + ((size_t)((n * HP + h + 1) * WP + 1)) * CI);
        for (int id = tid; id < WW * (CI / 2); id += 256) {
            int w = id >> 6, c2 = id & 63;
            dst[w * (CI / 2) + c2] =
                __halves2half2(s[(2 * c2) * 58 + w], s[(2 * c2 + 1) * 58 + w]);
        }
    } else if (bid < TBLK + HBLK) {
        int n = bid - TBLK;
        uint4 z = make_uint4(0, 0, 0, 0);
        __half* b0 = g_xh + (size_t)(n * HP + 0)  * WP * CI;
        __half* b1 = g_xh + (size_t)(n * HP + 57) * WP * CI;
        for (int i = tid; i < WP * CI / 8; i += 256) {
            reinterpret_cast<uint4*>(b0)[i] = z;
            reinterpret_cast<uint4*>(b1)[i] = z;
        }
        for (int i = tid; i < 56 * 2 * 16; i += 256) {
            int r = i >> 5; int e = (i >> 4) & 1; int q = i & 15;
            __half* eb = g_xh + (size_t)((n * HP + 1 + r) * WP + e * 57) * CI;
            reinterpret_cast<uint4*>(eb)[q] = z;
        }
    } else {
        int i0 = (bid - TBLK - HBLK) * 8192;
        for (int k = tid; k < 8192; k += 256) {
            int i = i0 + k;
            int kw = i % 3; int t = i / 3;
            int kh = t % 3; t /= 3;
            int ci = t % CI; int co = t / CI;
            float v = rintf(W[i] * 128.0f);      // exact integer, exact in fp16
            g_wh[(size_t)((kh * 3 + kw) * CO + co) * CI + ci] = __float2half_rn(v);
        }
    }
}

// ---------------- GEMM (HMMA, 2 CTAs/SM, unrolled x3 mainloop) ----------------
// CTA: 128 pix x 128 co, 256 threads. K: 18 chunks of 64 ci (9 taps x 2 halves).
// 8 warps 4m x 2n, warp tile 32x64, mma m16n8k16 f32.f16. 2 CTAs resident/SM.
// Mainloop unrolled by 3 so stage-slot indices and tap offsets are constants.

#define ROWB    144                 // 128B data + 16B pad
#define BOFF    (128 * ROWB)        // B tile offset within a stage
#define STAGE   (256 * ROWB)        // 36864
#define NT      18
#define HDR     512
#define SMEM_DYN (HDR + 3 * STAGE)  // 111104 -> 2 CTAs/SM

__device__ __forceinline__ void ldsm_x4(uint32_t addr, uint32_t& r0, uint32_t& r1,
                                        uint32_t& r2, uint32_t& r3) {
    asm volatile("ldmatrix.sync.aligned.m8n8.x4.shared.b16 {%0,%1,%2,%3}, [%4];\n"
                 : "=r"(r0), "=r"(r1), "=r"(r2), "=r"(r3) : "r"(addr));
}

__global__ void __launch_bounds__(256, 2) qconv_gemm(const float* __restrict__ bias,
                                                     float* __restrict__ out) {
    extern __shared__ char smem[];
    float* bq = reinterpret_cast<float*>(smem);
    const uint32_t sb = (uint32_t)__cvta_generic_to_shared(smem);

    const int tid = threadIdx.x;
    const int m_base  = blockIdx.x * 128;
    const int co_base = blockIdx.y * 128;

    if (tid < 128) bq[tid] = rintf(bias[co_base + tid] * 128.0f);

    // compressed cp.async endpoint state: piece i: row = (tid>>3) + 32*i
    const char* xh = reinterpret_cast<const char*>(g_xh);
    const char* wh = reinterpret_cast<const char*>(g_wh);
    const int row0 = tid >> 3, ch0 = (tid & 7) * 16;
    const char* aSrc[4];
    #pragma unroll
    for (int i = 0; i < 4; i++) {
        int p = m_base + row0 + 32 * i;
        int ni = p / PIX; int rem = p - ni * PIX;
        int h = rem / WW; int w = rem - h * WW;
        aSrc[i] = xh + ((size_t)((ni * HP + h) * WP + w)) * 256 + ch0;  // window top-left
    }
    const char* bSrc0 = wh + (size_t)(co_base + row0) * 256 + ch0;
    const uint32_t aDst0 = sb + HDR + row0 * ROWB + ch0;
    const uint32_t bDst0 = sb + HDR + BOFF + row0 * ROWB + ch0;

    // chunk T (compile-time): kc = T>>1, hf = T&1; all offsets constant-folded
    #define ISSUE(T, SLOT) do {                                                        \
        constexpr int _kc = (T) >> 1, _hf = (T) & 1;                                   \
        constexpr uint32_t _ao = (uint32_t)(((_kc / 3) * WP + (_kc % 3)) * 256 + _hf * 128); \
        constexpr uint32_t _bo = (uint32_t)(_kc * (CO * 256) + _hf * 128);             \
        constexpr uint32_t _so = (SLOT) * STAGE;                                       \
        _Pragma("unroll")                                                              \
        for (int _i = 0; _i < 4; _i++)                                                 \
            asm volatile("cp.async.cg.shared.global [%0], [%1], 16;\n"                 \
                         :: "r"(aDst0 + _so + _i * (32 * ROWB)), "l"(aSrc[_i] + _ao)); \
        _Pragma("unroll")                                                              \
        for (int _i = 0; _i < 4; _i++)                                                 \
            asm volatile("cp.async.cg.shared.global [%0], [%1], 16;\n"                 \
                         :: "r"(bDst0 + _so + _i * (32 * ROWB)),                       \
                            "l"(bSrc0 + _bo + (size_t)_i * 8192));                     \
        asm volatile("cp.async.commit_group;\n" ::: "memory");                         \
    } while (0)

    const int warp = tid >> 5, lane = tid & 31;
    const int warp_m = (warp & 3) * 32;
    const int warp_n = (warp >> 2) * 64;

    float acc[2][8][4];
    #pragma unroll
    for (int i = 0; i < 2; i++)
        #pragma unroll
        for (int j = 0; j < 8; j++)
            #pragma unroll
            for (int k = 0; k < 4; k++) acc[i][j][k] = 0.0f;

    const uint32_t aoff0 = (uint32_t)((warp_m + (lane & 15)) * ROWB + (lane >> 4) * 16);
    const uint32_t boff0 = (uint32_t)(BOFF + (warp_n + (lane & 7) + ((lane >> 4) << 3)) * ROWB
                                      + ((lane >> 3) & 1) * 16);

    // compute chunk in stage slot SLOT (compile-time)
    #define COMPUTE(SLOT) do {                                                         \
        constexpr uint32_t _sbase = HDR + (SLOT) * STAGE;                              \
        uint32_t sA = sb + _sbase;                                                     \
        _Pragma("unroll")                                                              \
        for (int k16 = 0; k16 < 4; k16++) {                                            \
            uint32_t a[2][4];                                                          \
            _Pragma("unroll")                                                          \
            for (int mf = 0; mf < 2; mf++)                                             \
                ldsm_x4(sA + aoff0 + mf * (16 * ROWB) + k16 * 32,                      \
                        a[mf][0], a[mf][1], a[mf][2], a[mf][3]);                       \
            uint32_t b[8][2];                                                          \
            _Pragma("unroll")                                                          \
            for (int j = 0; j < 4; j++) {                                              \
                uint32_t r0, r1, r2, r3;                                               \
                ldsm_x4(sA + boff0 + j * (16 * ROWB) + k16 * 32, r0, r1, r2, r3);      \
                b[2*j][0] = r0; b[2*j][1] = r1; b[2*j+1][0] = r2; b[2*j+1][1] = r3;    \
            }                                                                          \
            _Pragma("unroll")                                                          \
            for (int mf = 0; mf < 2; mf++)                                             \
                _Pragma("unroll")                                                      \
                for (int nf = 0; nf < 8; nf++) {                                       \
                    asm volatile(                                                      \
                        "mma.sync.aligned.m16n8k16.row.col.f32.f16.f16.f32 "           \
                        "{%0,%1,%2,%3}, {%4,%5,%6,%7}, {%8,%9}, {%0,%1,%2,%3};\n"      \
                        : "+f"(acc[mf][nf][0]), "+f"(acc[mf][nf][1]),                  \
                          "+f"(acc[mf][nf][2]), "+f"(acc[mf][nf][3])                   \
                        : "r"(a[mf][0]), "r"(a[mf][1]), "r"(a[mf][2]), "r"(a[mf][3]),  \
                          "r"(b[nf][0]), "r"(b[nf][1]));                               \
                }                                                                      \
        }                                                                              \
    } while (0)

    #define CHUNK(T, SLOT, NXT_SLOT) do {                                              \
        asm volatile("cp.async.wait_group 1;\n" ::: "memory");                         \
        __syncthreads();                                                               \
        if ((T) + 2 < NT) ISSUE((T) + 2, NXT_SLOT);                                    \
        else asm volatile("cp.async.commit_group;\n" ::: "memory");                    \
        COMPUTE(SLOT);                                                                 \
    } while (0)

    // prologue: fill 2 of 3 stages
    ISSUE(0, 0); ISSUE(1, 1);

    // NT = 18 chunks, slots cycle 0,1,2; next-issue slot = (s+2)%3 — all constants
    CHUNK(0, 0, 2);  CHUNK(1, 1, 0);  CHUNK(2, 2, 1);
    CHUNK(3, 0, 2);  CHUNK(4, 1, 0);  CHUNK(5, 2, 1);
    CHUNK(6, 0, 2);  CHUNK(7, 1, 0);  CHUNK(8, 2, 1);
    CHUNK(9, 0, 2);  CHUNK(10, 1, 0); CHUNK(11, 2, 1);
    CHUNK(12, 0, 2); CHUNK(13, 1, 0); CHUNK(14, 2, 1);
    CHUNK(15, 0, 2); CHUNK(16, 1, 0); CHUNK(17, 2, 1);

    // epilogue: out[n][co][h][w] = acc/128 + round(b*128)
    const float inv = 0.0078125f;
    #pragma unroll
    for (int mf = 0; mf < 2; mf++) {
        #pragma unroll
        for (int hsel = 0; hsel < 2; hsel++) {
            int m = warp_m + mf * 16 + (lane >> 2) + hsel * 8;
            int p = m_base + m;
            int ni = p / PIX; int rem = p - ni * PIX;
            int h = rem / WW; int w = rem - h * WW;
            float* op = out + (size_t)ni * CO * PIX + h * WW + w;
            #pragma unroll
            for (int nf = 0; nf < 8; nf++) {
                int col = warp_n + nf * 8 + 2 * (lane & 3);
                int co  = co_base + col;
                op[(size_t)co * PIX]       = acc[mf][nf][hsel*2 + 0] * inv + bq[col];
                op[(size_t)(co + 1) * PIX] = acc[mf][nf][hsel*2 + 1] * inv + bq[col + 1];
            }
        }
    }
}

// ---------------- launch ----------------
extern "C" void kernel_launch(void* const* d_in, const int* in_sizes, int n_in,
                              void* d_out, int out_size) {
    const float* x = (const float*)d_in[0];
    const float* W = (const float*)d_in[1];
    const float* b = (const float*)d_in[2];
    float* out = (float*)d_out;

    prep<<<TBLK + HBLK + WBLK, 256>>>(x, W);

    cudaFuncSetAttribute(qconv_gemm, cudaFuncAttributeMaxDynamicSharedMemorySize, SMEM_DYN);
    qconv_gemm<<<dim3(MTOT / 128, CO / 128), 256, SMEM_DYN>>>(b, out);
}

// round 17
// speedup vs baseline: 1.2971x; 1.0190x over previous
#include <cuda_runtime.h>
#include <cuda_fp16.h>
#include <cstdint>

// ---------------- problem constants ----------------
#define NIMG 32
#define CI   128
#define HH   56
#define WW   56
#define CO   256
#define HP   58
#define WP   58
#define PIX  (HH*WW)          // 3136
#define MTOT (NIMG*PIX)       // 100352

// fp16 scratch (static device globals: allowed)
__device__ __align__(1024) __half g_xh[(size_t)NIMG*HP*WP*CI];  // NHWC + halo
__device__ __align__(1024) __half g_wh[(size_t)9*CO*CI];        // [kc][co][ci]

// ---------------- fused prep kernel (champion, unchanged) ----------------
#define TBLK 1792
#define HBLK 32
#define WBLK 36

__global__ void __launch_bounds__(256) prep(const float* __restrict__ x,
                                            const float* __restrict__ W) {
    const int bid = blockIdx.x, tid = threadIdx.x;

    if (bid < TBLK) {
        __shared__ __half s[CI * 58];
        __half2* s2 = reinterpret_cast<__half2*>(s);
        int h = bid % 56, n = bid / 56;
        const float* xp = x + ((size_t)n * CI) * PIX + h * WW;
        for (int id = tid; id < CI * 14; id += 256) {
            int ci = id / 14, w4 = id % 14;
            float4 v = *reinterpret_cast<const float4*>(xp + (size_t)ci * PIX + w4 * 4);
            int si = ci * 29 + w4 * 2;
            s2[si]     = __halves2half2(__float2half_rn(v.x), __float2half_rn(v.y));
            s2[si + 1] = __halves2half2(__float2half_rn(v.z), __float2half_rn(v.w));
        }
        __syncthreads();
        __half2* dst = reinterpret_cast<__half2*>(
            g_xh + ((size_t)((n * HP + h + 1) * WP + 1)) * CI);
        for (int id = tid; id < WW * (CI / 2); id += 256) {
            int w = id >> 6, c2 = id & 63;
            dst[w * (CI / 2) + c2] =
                __halves2half2(s[(2 * c2) * 58 + w], s[(2 * c2 + 1) * 58 + w]);
        }
    } else if (bid < TBLK + HBLK) {
        int n = bid - TBLK;
        uint4 z = make_uint4(0, 0, 0, 0);
        __half* b0 = g_xh + (size_t)(n * HP + 0)  * WP * CI;
        __half* b1 = g_xh + (size_t)(n * HP + 57) * WP * CI;
        for (int i = tid; i < WP * CI / 8; i += 256) {
            reinterpret_cast<uint4*>(b0)[i] = z;
            reinterpret_cast<uint4*>(b1)[i] = z;
        }
        for (int i = tid; i < 56 * 2 * 16; i += 256) {
            int r = i >> 5; int e = (i >> 4) & 1; int q = i & 15;
            __half* eb = g_xh + (size_t)((n * HP + 1 + r) * WP + e * 57) * CI;
            reinterpret_cast<uint4*>(eb)[q] = z;
        }
    } else {
        int i0 = (bid - TBLK - HBLK) * 8192;
        for (int k = tid; k < 8192; k += 256) {
            int i = i0 + k;
            int kw = i % 3; int t = i / 3;
            int kh = t % 3; t /= 3;
            int ci = t % CI; int co = t / CI;
            float v = rintf(W[i] * 128.0f);      // exact integer, exact in fp16
            g_wh[(size_t)((kh * 3 + kw) * CO + co) * CI + ci] = __float2half_rn(v);
        }
    }
}

// ---------------- GEMM (HMMA, 64x64 warp tiles, unrolled x3, 2 CTAs/SM) -------
// CTA: 128 pix x 128 co, 128 threads, 4 warps (2m x 2n), warp tile 64x64.
// K: 18 chunks of 64 ci. 3 stages, constant-folded mainloop. 2 CTAs/SM.
// Per-chunk smem/SM: 192 KB (vs 256 KB at 32x64 tiles) -> higher overlap ceiling.

#define ROWB    144                 // 128B data + 16B pad
#define BOFF    (128 * ROWB)        // B tile offset within a stage
#define STAGE   (256 * ROWB)        // 36864
#define NT      18
#define HDR     512
#define SMEM_DYN (HDR + 3 * STAGE)  // 111104 -> 2 CTAs/SM

__device__ __forceinline__ void ldsm_x4(uint32_t addr, uint32_t& r0, uint32_t& r1,
                                        uint32_t& r2, uint32_t& r3) {
    asm volatile("ldmatrix.sync.aligned.m8n8.x4.shared.b16 {%0,%1,%2,%3}, [%4];\n"
                 : "=r"(r0), "=r"(r1), "=r"(r2), "=r"(r3) : "r"(addr));
}

__global__ void __launch_bounds__(128, 2) qconv_gemm(const float* __restrict__ bias,
                                                     float* __restrict__ out) {
    extern __shared__ char smem[];
    float* bq = reinterpret_cast<float*>(smem);
    const uint32_t sb = (uint32_t)__cvta_generic_to_shared(smem);

    const int tid = threadIdx.x;
    const int m_base  = blockIdx.x * 128;
    const int co_base = blockIdx.y * 128;

    bq[tid] = rintf(bias[co_base + tid] * 128.0f);

    // cp.async endpoints: row0 = tid>>3 in [0,16); pieces at 16-row strides
    const char* xh = reinterpret_cast<const char*>(g_xh);
    const char* wh = reinterpret_cast<const char*>(g_wh);
    const int row0 = tid >> 3, ch0 = (tid & 7) * 16;
    const char* aSrc[8];
    #pragma unroll
    for (int i = 0; i < 8; i++) {
        int p = m_base + row0 + 16 * i;
        int ni = p / PIX; int rem = p - ni * PIX;
        int h = rem / WW; int w = rem - h * WW;
        aSrc[i] = xh + ((size_t)((ni * HP + h) * WP + w)) * 256 + ch0;  // window top-left
    }
    const char* bSrc0 = wh + (size_t)(co_base + row0) * 256 + ch0;
    const uint32_t aDst0 = sb + HDR + row0 * ROWB + ch0;
    const uint32_t bDst0 = sb + HDR + BOFF + row0 * ROWB + ch0;

    // chunk T (compile-time): kc = T>>1, hf = T&1; all offsets constant-folded
    #define ISSUE(T, SLOT) do {                                                        \
        constexpr int _kc = (T) >> 1, _hf = (T) & 1;                                   \
        constexpr uint32_t _ao = (uint32_t)(((_kc / 3) * WP + (_kc % 3)) * 256 + _hf * 128); \
        constexpr uint32_t _bo = (uint32_t)(_kc * (CO * 256) + _hf * 128);             \
        constexpr uint32_t _so = (SLOT) * STAGE;                                       \
        _Pragma("unroll")                                                              \
        for (int _i = 0; _i < 8; _i++)                                                 \
            asm volatile("cp.async.cg.shared.global [%0], [%1], 16;\n"                 \
                         :: "r"(aDst0 + _so + _i * (16 * ROWB)), "l"(aSrc[_i] + _ao)); \
        _Pragma("unroll")                                                              \
        for (int _i = 0; _i < 8; _i++)                                                 \
            asm volatile("cp.async.cg.shared.global [%0], [%1], 16;\n"                 \
                         :: "r"(bDst0 + _so + _i * (16 * ROWB)),                       \
                            "l"(bSrc0 + _bo + (size_t)_i * 4096));                     \
        asm volatile("cp.async.commit_group;\n" ::: "memory");                         \
    } while (0)

    const int warp = tid >> 5, lane = tid & 31;
    const int warp_m = (warp & 1) * 64;
    const int warp_n = (warp >> 1) * 64;

    float acc[4][8][4];
    #pragma unroll
    for (int i = 0; i < 4; i++)
        #pragma unroll
        for (int j = 0; j < 8; j++)
            #pragma unroll
            for (int k = 0; k < 4; k++) acc[i][j][k] = 0.0f;

    const uint32_t aoff0 = (uint32_t)((warp_m + (lane & 15)) * ROWB + (lane >> 4) * 16);
    const uint32_t boff0 = (uint32_t)(BOFF + (warp_n + (lane & 7) + ((lane >> 4) << 3)) * ROWB
                                      + ((lane >> 3) & 1) * 16);

    // compute chunk in stage slot SLOT (compile-time)
    #define COMPUTE(SLOT) do {                                                         \
        constexpr uint32_t _sbase = HDR + (SLOT) * STAGE;                              \
        uint32_t sA = sb + _sbase;                                                     \
        _Pragma("unroll")                                                              \
        for (int k16 = 0; k16 < 4; k16++) {                                            \
            uint32_t a[4][4];                                                          \
            _Pragma("unroll")                                                          \
            for (int mf = 0; mf < 4; mf++)                                             \
                ldsm_x4(sA + aoff0 + mf * (16 * ROWB) + k16 * 32,                      \
                        a[mf][0], a[mf][1], a[mf][2], a[mf][3]);                       \
            uint32_t b[8][2];                                                          \
            _Pragma("unroll")                                                          \
            for (int j = 0; j < 4; j++) {                                              \
                uint32_t r0, r1, r2, r3;                                               \
                ldsm_x4(sA + boff0 + j * (16 * ROWB) + k16 * 32, r0, r1, r2, r3);      \
                b[2*j][0] = r0; b[2*j][1] = r1; b[2*j+1][0] = r2; b[2*j+1][1] = r3;    \
            }                                                                          \
            _Pragma("unroll")                                                          \
            for (int mf = 0; mf < 4; mf++)                                             \
                _Pragma("unroll")                                                      \
                for (int nf = 0; nf < 8; nf++) {                                       \
                    asm volatile(                                                      \
                        "mma.sync.aligned.m16n8k16.row.col.f32.f16.f16.f32 "           \
                        "{%0,%1,%2,%3}, {%4,%5,%6,%7}, {%8,%9}, {%0,%1,%2,%3};\n"      \
                        : "+f"(acc[mf][nf][0]), "+f"(acc[mf][nf][1]),                  \
                          "+f"(acc[mf][nf][2]), "+f"(acc[mf][nf][3])                   \
                        : "r"(a[mf][0]), "r"(a[mf][1]), "r"(a[mf][2]), "r"(a[mf][3]),  \
                          "r"(b[nf][0]), "r"(b[nf][1]));                               \
                }                                                                      \
        }                                                                              \
    } while (0)

    #define CHUNK(T, SLOT, NXT_SLOT) do {                                              \
        asm volatile("cp.async.wait_group 1;\n" ::: "memory");                         \
        __syncthreads();                                                               \
        if ((T) + 2 < NT) ISSUE((T) + 2, NXT_SLOT);                                    \
        else asm volatile("cp.async.commit_group;\n" ::: "memory");                    \
        COMPUTE(SLOT);                                                                 \
    } while (0)

    // prologue: fill 2 of 3 stages
    ISSUE(0, 0); ISSUE(1, 1);

    CHUNK(0, 0, 2);  CHUNK(1, 1, 0);  CHUNK(2, 2, 1);
    CHUNK(3, 0, 2);  CHUNK(4, 1, 0);  CHUNK(5, 2, 1);
    CHUNK(6, 0, 2);  CHUNK(7, 1, 0);  CHUNK(8, 2, 1);
    CHUNK(9, 0, 2);  CHUNK(10, 1, 0); CHUNK(11, 2, 1);
    CHUNK(12, 0, 2); CHUNK(13, 1, 0); CHUNK(14, 2, 1);
    CHUNK(15, 0, 2); CHUNK(16, 1, 0); CHUNK(17, 2, 1);

    // epilogue: out[n][co][h][w] = acc/128 + round(b*128)
    const float inv = 0.0078125f;
    #pragma unroll
    for (int mf = 0; mf < 4; mf++) {
        #pragma unroll
        for (int hsel = 0; hsel < 2; hsel++) {
            int m = warp_m + mf * 16 + (lane >> 2) + hsel * 8;
            int p = m_base + m;
            int ni = p / PIX; int rem = p - ni * PIX;
            int h = rem / WW; int w = rem - h * WW;
            float* op = out + (size_t)ni * CO * PIX + h * WW + w;
            #pragma unroll
            for (int nf = 0; nf < 8; nf++) {
                int col = warp_n + nf * 8 + 2 * (lane & 3);
                int co  = co_base + col;
                op[(size_t)co * PIX]       = acc[mf][nf][hsel*2 + 0] * inv + bq[col];
                op[(size_t)(co + 1) * PIX] = acc[mf][nf][hsel*2 + 1] * inv + bq[col + 1];
            }
        }
    }
}

// ---------------- launch ----------------
extern "C" void kernel_launch(void* const* d_in, const int* in_sizes, int n_in,
                              void* d_out, int out_size) {
    const float* x = (const float*)d_in[0];
    const float* W = (const float*)d_in[1];
    const float* b = (const float*)d_in[2];
    float* out = (float*)d_out;

    prep<<<TBLK + HBLK + WBLK, 256>>>(x, W);

    cudaFuncSetAttribute(qconv_gemm, cudaFuncAttributeMaxDynamicSharedMemorySize, SMEM_DYN);
    qconv_gemm<<<dim3(MTOT / 128, CO / 128), 128, SMEM_DYN>>>(b, out);
}